// round 14
// baseline (speedup 1.0000x reference)
#include <cuda_runtime.h>
#include <cuda_fp16.h>

#define N_NODES 10000
#define N_EDGES 640000
#define D       128
#define D_IN3   384   // (K_HOPS+1)*D
#define LN_EPS  1e-5f

// ---------------- scratch (device globals; no allocation allowed) -----------
__device__ int      g_cnt [N_NODES];        // in-degree histogram (zeroed by scatter for next call)
__device__ int      g_row [N_NODES + 1];    // CSR row offsets (by dst)
__device__ float    g_norm[N_NODES];
__device__ int      g_rank[N_EDGES];        // edge rank within its dst segment
__device__ int4     g_erec[N_EDGES];        // {src*256, c1, c2, 0} sorted by dst
__device__ uint2    g_h16 [N_NODES * 32];   // h  as fp16 (256B rows)
__device__ uint2    g_f1h [N_NODES * 32];   // f1 as fp16
__device__ uint2    g_f2h [N_NODES * 32];   // f2 as fp16
__device__ float2   g_wr  [48 * 128 * 4];   // W reordered: [k0][n][tg]
__device__ unsigned g_ctrA, g_ctrB;         // hop work counters

// ---------------- fused prep: h->fp16 conv | dst hist+rank | W reorder --------
#define PREP_CONV_BLOCKS 1250
#define PREP_HIST_BLOCKS 625
#define PREP_WR_BLOCKS   96
#define PREP_BLOCKS (PREP_CONV_BLOCKS + PREP_HIST_BLOCKS + PREP_WR_BLOCKS)

__global__ void __launch_bounds__(256) prep_kernel(
    const float4* __restrict__ h4,
    const int*    __restrict__ dst,
    const float*  __restrict__ W)
{
    int b   = blockIdx.x;
    int tid = threadIdx.x;

    if (b < PREP_CONV_BLOCKS) {
        int i = b * 256 + tid;
        if (i < N_NODES * 32) {
            float4 v = __ldg(&h4[i]);
            __half2 a = __floats2half2_rn(v.x, v.y);
            __half2 c = __floats2half2_rn(v.z, v.w);
            uint2 o;
            o.x = *reinterpret_cast<unsigned*>(&a);
            o.y = *reinterpret_cast<unsigned*>(&c);
            g_h16[i] = o;
        }
    } else if (b < PREP_CONV_BLOCKS + PREP_HIST_BLOCKS) {
        int t  = (b - PREP_CONV_BLOCKS) * 256 + tid;   // 4 edges per thread
        int4 d4 = __ldg(&((const int4*)dst)[t]);
        int r0 = atomicAdd(&g_cnt[d4.x], 1);
        int r1 = atomicAdd(&g_cnt[d4.y], 1);
        int r2 = atomicAdd(&g_cnt[d4.z], 1);
        int r3 = atomicAdd(&g_cnt[d4.w], 1);
        ((int4*)g_rank)[t] = make_int4(r0, r1, r2, r3);
    } else {
        int idx = (b - PREP_CONV_BLOCKS - PREP_HIST_BLOCKS) * 256 + tid;  // 24576
        int tg = idx & 3;
        int n  = (idx >> 2) & 127;
        int k0 = idx >> 9;
        g_wr[idx] = make_float2(__ldg(&W[n * D_IN3 + k0 * 8 + tg]),
                                __ldg(&W[n * D_IN3 + k0 * 8 + tg + 4]));
    }
}

// ---------------- single-block prefix scan + norm + counter reset -------------
__global__ void __launch_bounds__(1024) scan_kernel() {
    __shared__ int ts[1024];
    int t = threadIdx.x;
    if (t == 0) { g_ctrA = 0; g_ctrB = 0; }
    int b = t * 10;
    int e = min(b + 10, N_NODES);

    int s = 0;
    for (int i = b; i < e; i++) s += g_cnt[i];
    ts[t] = s;
    __syncthreads();

    for (int o = 1; o < 1024; o <<= 1) {
        int v = (t >= o) ? ts[t - o] : 0;
        __syncthreads();
        ts[t] += v;
        __syncthreads();
    }
    int off = (t == 0) ? 0 : ts[t - 1];

    for (int i = b; i < e; i++) {
        int c = g_cnt[i];
        g_row[i]  = off;
        g_norm[i] = rsqrtf(fmaxf((float)c, 1.0f));
        off += c;
    }
    if (t == 1023) g_row[N_NODES] = N_EDGES;
}

// ---------------- scatter edges into CSR order (NO atomics) -------------------
// Also zeroes g_cnt for the NEXT invocation (g_cnt is zero-initialized at
// module load, so every call sees cnt==0 at entry; deterministic).
__global__ void __launch_bounds__(256) scatter_kernel(
    const float* __restrict__ ew,
    const int*   __restrict__ src,
    const int*   __restrict__ dst)
{
    int t = blockIdx.x * blockDim.x + threadIdx.x;   // 4 edges per thread
    int4   d4 = __ldg(&((const int4*)dst)[t]);
    int4   s4 = __ldg(&((const int4*)src)[t]);
    float4 w4 = __ldg(&((const float4*)ew)[t]);
    int4   r4 = __ldg(&((const int4*)g_rank)[t]);

    int p0 = __ldg(&g_row[d4.x]) + r4.x;
    int p1 = __ldg(&g_row[d4.y]) + r4.y;
    int p2 = __ldg(&g_row[d4.z]) + r4.z;
    int p3 = __ldg(&g_row[d4.w]) + r4.w;

    float n0 = __ldg(&g_norm[s4.x]);
    float n1 = __ldg(&g_norm[s4.y]);
    float n2 = __ldg(&g_norm[s4.z]);
    float n3 = __ldg(&g_norm[s4.w]);

    float c10 = w4.x * n0, c11 = w4.y * n1, c12 = w4.z * n2, c13 = w4.w * n3;

    g_erec[p0] = make_int4(s4.x * 256, __float_as_int(c10), __float_as_int(c10 * n0), 0);
    g_erec[p1] = make_int4(s4.y * 256, __float_as_int(c11), __float_as_int(c11 * n1), 0);
    g_erec[p2] = make_int4(s4.z * 256, __float_as_int(c12), __float_as_int(c12 * n2), 0);
    g_erec[p3] = make_int4(s4.w * 256, __float_as_int(c13), __float_as_int(c13 * n3), 0);

    // reset histogram for next launch (scan has already consumed it)
    if (t < N_NODES / 4) ((int4*)g_cnt)[t] = make_int4(0, 0, 0, 0);
}

// ---------------- gather hop: half-warp per edge (2 edges / warp-iteration) ---
// Half h (lanes 16h..16h+15) owns one edge per pair; lane sub=lane&15 gathers
// uint4 (16B = 8 halves). 4 blocks/SM -> 64 regs for deeper LDG batching.
template <int SECOND>
__global__ void __launch_bounds__(256, 4) hop_csr(
    const uint2* __restrict__ feat16,
    unsigned*    __restrict__ ctr,
    uint4*       __restrict__ outh4)
{
    __shared__ __align__(8) uint2 stage[8][32];   // {byte_off, coef_bits}

    int lane = threadIdx.x & 31;
    int warp = threadIdx.x >> 5;
    int half = lane >> 4;          // 0 or 1
    int sub  = lane & 15;          // 0..15
    uint2* sbuf = stage[warp];
    const char* fbase = (const char*)feat16 + sub * 16;

    for (;;) {
        unsigned node = 0;
        if (lane == 0) node = atomicAdd(ctr, 1u);
        node = __shfl_sync(0xffffffffu, node, 0);
        if (node >= N_NODES) break;

        int beg = g_row[node];
        int end = g_row[node + 1];

        unsigned long long a0 = 0, a1 = 0, a2 = 0, a3 = 0;
        int base = beg;

        for (; base + 32 <= end; base += 32) {
            int4 rec = __ldg(&g_erec[base + lane]);
            unsigned cb = SECOND ? (unsigned)rec.z : (unsigned)rec.y;
            __syncwarp();
            sbuf[lane] = make_uint2((unsigned)rec.x, cb);
            __syncwarp();
#pragma unroll
            for (int i = 0; i < 16; i++) {
                uint2 e = sbuf[2 * i + half];            // LDS.64, 2-addr bcast
                unsigned long long cc;
                asm("mov.b64 %0, {%1, %1};" : "=l"(cc) : "r"(e.y));
                uint4 v = __ldg((const uint4*)(fbase + e.x));
                float2 f0 = __half22float2(*reinterpret_cast<__half2*>(&v.x));
                float2 f1 = __half22float2(*reinterpret_cast<__half2*>(&v.y));
                float2 f2 = __half22float2(*reinterpret_cast<__half2*>(&v.z));
                float2 f3 = __half22float2(*reinterpret_cast<__half2*>(&v.w));
                unsigned long long p0, p1, p2, p3;
                asm("mov.b64 %0, {%1, %2};" : "=l"(p0) : "f"(f0.x), "f"(f0.y));
                asm("mov.b64 %0, {%1, %2};" : "=l"(p1) : "f"(f1.x), "f"(f1.y));
                asm("mov.b64 %0, {%1, %2};" : "=l"(p2) : "f"(f2.x), "f"(f2.y));
                asm("mov.b64 %0, {%1, %2};" : "=l"(p3) : "f"(f3.x), "f"(f3.y));
                asm("fma.rn.f32x2 %0, %1, %2, %0;" : "+l"(a0) : "l"(cc), "l"(p0));
                asm("fma.rn.f32x2 %0, %1, %2, %0;" : "+l"(a1) : "l"(cc), "l"(p1));
                asm("fma.rn.f32x2 %0, %1, %2, %0;" : "+l"(a2) : "l"(cc), "l"(p2));
                asm("fma.rn.f32x2 %0, %1, %2, %0;" : "+l"(a3) : "l"(cc), "l"(p3));
            }
        }

        int rem = end - base;
        if (rem > 0) {
            __syncwarp();
            if (lane < rem) {
                int4 rec = __ldg(&g_erec[base + lane]);
                unsigned cb = SECOND ? (unsigned)rec.z : (unsigned)rec.y;
                sbuf[lane] = make_uint2((unsigned)rec.x, cb);
            } else {
                sbuf[lane] = make_uint2(0u, 0u);
            }
            __syncwarp();
            int pairs = (rem + 1) >> 1;
            for (int i = 0; i < pairs; i++) {
                uint2 e = sbuf[2 * i + half];
                unsigned long long cc;
                asm("mov.b64 %0, {%1, %1};" : "=l"(cc) : "r"(e.y));
                uint4 v = __ldg((const uint4*)(fbase + e.x));
                float2 f0 = __half22float2(*reinterpret_cast<__half2*>(&v.x));
                float2 f1 = __half22float2(*reinterpret_cast<__half2*>(&v.y));
                float2 f2 = __half22float2(*reinterpret_cast<__half2*>(&v.z));
                float2 f3 = __half22float2(*reinterpret_cast<__half2*>(&v.w));
                unsigned long long p0, p1, p2, p3;
                asm("mov.b64 %0, {%1, %2};" : "=l"(p0) : "f"(f0.x), "f"(f0.y));
                asm("mov.b64 %0, {%1, %2};" : "=l"(p1) : "f"(f1.x), "f"(f1.y));
                asm("mov.b64 %0, {%1, %2};" : "=l"(p2) : "f"(f2.x), "f"(f2.y));
                asm("mov.b64 %0, {%1, %2};" : "=l"(p3) : "f"(f3.x), "f"(f3.y));
                asm("fma.rn.f32x2 %0, %1, %2, %0;" : "+l"(a0) : "l"(cc), "l"(p0));
                asm("fma.rn.f32x2 %0, %1, %2, %0;" : "+l"(a1) : "l"(cc), "l"(p1));
                asm("fma.rn.f32x2 %0, %1, %2, %0;" : "+l"(a2) : "l"(cc), "l"(p2));
                asm("fma.rn.f32x2 %0, %1, %2, %0;" : "+l"(a3) : "l"(cc), "l"(p3));
            }
        }

        // merge even/odd-edge halves: lanes l and l^16 hold the two partials
        {
            unsigned long long b0 = __shfl_xor_sync(0xffffffffu, a0, 16);
            unsigned long long b1 = __shfl_xor_sync(0xffffffffu, a1, 16);
            unsigned long long b2 = __shfl_xor_sync(0xffffffffu, a2, 16);
            unsigned long long b3 = __shfl_xor_sync(0xffffffffu, a3, 16);
            asm("add.rn.f32x2 %0, %0, %1;" : "+l"(a0) : "l"(b0));
            asm("add.rn.f32x2 %0, %0, %1;" : "+l"(a1) : "l"(b1));
            asm("add.rn.f32x2 %0, %0, %1;" : "+l"(a2) : "l"(b2));
            asm("add.rn.f32x2 %0, %0, %1;" : "+l"(a3) : "l"(b3));
        }

        if (half == 0) {
            float x0, x1, x2, x3, x4, x5, x6, x7;
            asm("mov.b64 {%0, %1}, %2;" : "=f"(x0), "=f"(x1) : "l"(a0));
            asm("mov.b64 {%0, %1}, %2;" : "=f"(x2), "=f"(x3) : "l"(a1));
            asm("mov.b64 {%0, %1}, %2;" : "=f"(x4), "=f"(x5) : "l"(a2));
            asm("mov.b64 {%0, %1}, %2;" : "=f"(x6), "=f"(x7) : "l"(a3));
            __half2 h0 = __floats2half2_rn(x0, x1);
            __half2 h1 = __floats2half2_rn(x2, x3);
            __half2 h2 = __floats2half2_rn(x4, x5);
            __half2 h3 = __floats2half2_rn(x6, x7);
            uint4 o;
            o.x = *reinterpret_cast<unsigned*>(&h0);
            o.y = *reinterpret_cast<unsigned*>(&h1);
            o.z = *reinterpret_cast<unsigned*>(&h2);
            o.w = *reinterpret_cast<unsigned*>(&h3);
            outh4[node * 16 + sub] = o;
        }
    }
}

// ---------------- 3xTF32 helpers ---------------------------------------------
__device__ __forceinline__ unsigned f2tf(float x) {
    unsigned r;
    asm("cvt.rna.tf32.f32 %0, %1;" : "=r"(r) : "f"(x));
    return r;
}

__device__ __forceinline__ void mma8(float* d, const unsigned* a, const unsigned* b) {
    asm volatile("mma.sync.aligned.m16n8k8.row.col.f32.tf32.tf32.f32 "
                 "{%0,%1,%2,%3},{%4,%5,%6,%7},{%8,%9},{%0,%1,%2,%3};"
                 : "+f"(d[0]), "+f"(d[1]), "+f"(d[2]), "+f"(d[3])
                 : "r"(a[0]), "r"(a[1]), "r"(a[2]), "r"(a[3]),
                   "r"(b[0]), "r"(b[1]));
}

// ---------------- fused GEMM (3xTF32 mma) + bias + LayerNorm + ReLU ----------
// 512 threads (16 warps), TM=64 nodes/block -> halves W re-streaming.
// Warp w: rows [16*(w>>2), +16), cols [32*(w&3), +32).
#define SAPAD 388
#define SXPAD 132
#define TM_OUT 64
#define OUT_SMEM ((TM_OUT * SAPAD + TM_OUT * SXPAD + 2 * TM_OUT) * 4)

__global__ void __launch_bounds__(512) out_kernel(
    const float* __restrict__ h,
    const float* __restrict__ bias,
    const float* __restrict__ gamma,
    const float* __restrict__ beta,
    float* __restrict__ out)
{
    extern __shared__ float dyn[];
    float* sA  = dyn;                            // [TM_OUT][SAPAD]
    float* sx  = dyn + TM_OUT * SAPAD;           // [TM_OUT][SXPAD]
    float* smu = sx + TM_OUT * SXPAD;            // [TM_OUT]
    float* srs = smu + TM_OUT;                   // [TM_OUT]

    int tid   = threadIdx.x;
    int warp  = tid >> 5;
    int lane  = tid & 31;
    int node0 = blockIdx.x * TM_OUT;

    for (int idx = tid; idx < TM_OUT * 96; idx += 512) {
        int m = idx / 96, c = idx % 96;
        int node = min(node0 + m, N_NODES - 1);
        float4 v;
        if (c < 32) {
            v = __ldg(&((const float4*)h)[node * 32 + c]);
        } else {
            float nn = g_norm[node];
            const uint2* p16 = (c < 64) ? g_f1h : g_f2h;
            int cc = (c < 64) ? (c - 32) : (c - 64);
            uint2 u = p16[node * 32 + cc];
            float2 a = __half22float2(*reinterpret_cast<__half2*>(&u.x));
            float2 b = __half22float2(*reinterpret_cast<__half2*>(&u.y));
            v = make_float4(a.x * nn, a.y * nn, b.x * nn, b.y * nn);
        }
        *(float4*)&sA[m * SAPAD + c * 4] = v;
    }
    __syncthreads();

    int g  = lane >> 2;     // group 0..7
    int tg = lane & 3;      // thread-in-group 0..3
    int mrow = (warp >> 2) * 16;    // 0,16,32,48
    int wcol = (warp & 3) * 32;

    float acc[4][4];
#pragma unroll
    for (int nt = 0; nt < 4; nt++)
#pragma unroll
        for (int i = 0; i < 4; i++) acc[nt][i] = 0.0f;

#pragma unroll 4
    for (int k0 = 0; k0 < 48; k0++) {
        int kk = k0 * 8;
        float a0 = sA[(mrow + g    ) * SAPAD + kk + tg];
        float a1 = sA[(mrow + g + 8) * SAPAD + kk + tg];
        float a2 = sA[(mrow + g    ) * SAPAD + kk + tg + 4];
        float a3 = sA[(mrow + g + 8) * SAPAD + kk + tg + 4];

        unsigned ah[4] = { f2tf(a0), f2tf(a1), f2tf(a2), f2tf(a3) };
        unsigned al[4] = {
            f2tf(a0 - __uint_as_float(ah[0])),
            f2tf(a1 - __uint_as_float(ah[1])),
            f2tf(a2 - __uint_as_float(ah[2])),
            f2tf(a3 - __uint_as_float(ah[3]))
        };

#pragma unroll
        for (int nt = 0; nt < 4; nt++) {
            float2 wv = __ldg(&g_wr[k0 * 512 + (wcol + nt * 8) * 4 + lane]);
            unsigned bh[2] = { f2tf(wv.x), f2tf(wv.y) };
            unsigned bl[2] = {
                f2tf(wv.x - __uint_as_float(bh[0])),
                f2tf(wv.y - __uint_as_float(bh[1]))
            };
            mma8(acc[nt], ah, bh);
            mma8(acc[nt], al, bh);
            mma8(acc[nt], ah, bl);
        }
    }

#pragma unroll
    for (int nt = 0; nt < 4; nt++) {
        int col = wcol + nt * 8 + 2 * tg;
        float b0 = __ldg(&bias[col]);
        float b1 = __ldg(&bias[col + 1]);
        sx[(mrow + g    ) * SXPAD + col    ] = acc[nt][0] + b0;
        sx[(mrow + g    ) * SXPAD + col + 1] = acc[nt][1] + b1;
        sx[(mrow + g + 8) * SXPAD + col    ] = acc[nt][2] + b0;
        sx[(mrow + g + 8) * SXPAD + col + 1] = acc[nt][3] + b1;
    }
    __syncthreads();

    for (int m = warp; m < TM_OUT; m += 16) {
        float s = 0.0f, ss = 0.0f;
#pragma unroll
        for (int c = lane; c < D; c += 32) {
            float v = sx[m * SXPAD + c];
            s += v; ss += v * v;
        }
#pragma unroll
        for (int o = 16; o; o >>= 1) {
            s  += __shfl_xor_sync(0xffffffffu, s,  o);
            ss += __shfl_xor_sync(0xffffffffu, ss, o);
        }
        if (lane == 0) {
            float mu  = s * (1.0f / D);
            float var = ss * (1.0f / D) - mu * mu;
            smu[m] = mu;
            srs[m] = rsqrtf(var + LN_EPS);
        }
    }
    __syncthreads();

    int j     = tid & 127;
    int mbase = (tid >> 7) * 16;   // 0,16,32,48
    float gm = __ldg(&gamma[j]);
    float be = __ldg(&beta[j]);
#pragma unroll
    for (int mm = 0; mm < 16; mm++) {
        int m = mbase + mm;
        int node = node0 + m;
        if (node < N_NODES) {
            float v = (sx[m * SXPAD + j] - smu[m]) * srs[m] * gm + be;
            out[node * D + j] = fmaxf(v, 0.0f);
        }
    }
}

// ---------------- launch -----------------------------------------------------
extern "C" void kernel_launch(void* const* d_in, const int* in_sizes, int n_in,
                              void* d_out, int out_size)
{
    const float* h     = (const float*)d_in[0];
    const float* ew    = (const float*)d_in[1];
    const float* W     = (const float*)d_in[2];
    const float* bias  = (const float*)d_in[3];
    const float* gamma = (const float*)d_in[4];
    const float* beta  = (const float*)d_in[5];
    const int*   src   = (const int*)d_in[6];
    const int*   dst   = (const int*)d_in[7];
    float*       out   = (float*)d_out;

    void* h16Ptr;  cudaGetSymbolAddress(&h16Ptr,  g_h16);
    void* f1hPtr;  cudaGetSymbolAddress(&f1hPtr,  g_f1h);
    void* f2hPtr;  cudaGetSymbolAddress(&f2hPtr,  g_f2h);
    void* ctrAPtr; cudaGetSymbolAddress(&ctrAPtr, g_ctrA);
    void* ctrBPtr; cudaGetSymbolAddress(&ctrBPtr, g_ctrB);

    static bool attr_set = false;
    if (!attr_set) {
        cudaFuncSetAttribute(out_kernel,
                             cudaFuncAttributeMaxDynamicSharedMemorySize, OUT_SMEM);
        attr_set = true;
    }

    prep_kernel<<<PREP_BLOCKS, 256>>>((const float4*)h, dst, W);
    scan_kernel<<<1, 1024>>>();
    scatter_kernel<<<N_EDGES / 4 / 256, 256>>>(ew, src, dst);

    const int hopBlocks = 592;   // 4 blocks/SM * 148 SMs, persistent warps
    hop_csr<0><<<hopBlocks, 256>>>((const uint2*)h16Ptr, (unsigned*)ctrAPtr, (uint4*)f1hPtr);
    hop_csr<1><<<hopBlocks, 256>>>((const uint2*)f1hPtr, (unsigned*)ctrBPtr, (uint4*)f2hPtr);

    out_kernel<<<(N_NODES + TM_OUT - 1) / TM_OUT, 512, OUT_SMEM>>>(h, bias, gamma, beta, out);
}

// round 15
// speedup vs baseline: 1.1506x; 1.1506x over previous
#include <cuda_runtime.h>
#include <cuda_fp16.h>

#define N_NODES 10000
#define N_EDGES 640000
#define D       128
#define D_IN3   384   // (K_HOPS+1)*D
#define LN_EPS  1e-5f

// ---------------- scratch (device globals; no allocation allowed) -----------
__device__ int      g_cnt [N_NODES];        // in-degree histogram (zeroed by scatter for next call)
__device__ int      g_row [N_NODES + 1];    // CSR row offsets (by dst)
__device__ float    g_norm[N_NODES];
__device__ int      g_rank[N_EDGES];        // edge rank within its dst segment
__device__ int4     g_erec[N_EDGES];        // {src*256, c1, c2, 0} sorted by dst
__device__ uint2    g_h16 [N_NODES * 32];   // h  as fp16 (256B rows)
__device__ uint2    g_f1h [N_NODES * 32];   // f1 as fp16
__device__ uint2    g_f2h [N_NODES * 32];   // f2 as fp16
__device__ float2   g_wr  [48 * 128 * 4];   // W reordered: [k0][n][tg]
__device__ unsigned g_ctrA, g_ctrB;         // hop work counters

// ---------------- fused prep: h->fp16 conv | dst hist+rank | W reorder --------
#define PREP_CONV_BLOCKS 1250
#define PREP_HIST_BLOCKS 625
#define PREP_WR_BLOCKS   96
#define PREP_BLOCKS (PREP_CONV_BLOCKS + PREP_HIST_BLOCKS + PREP_WR_BLOCKS)

__global__ void __launch_bounds__(256) prep_kernel(
    const float4* __restrict__ h4,
    const int*    __restrict__ dst,
    const float*  __restrict__ W)
{
    int b   = blockIdx.x;
    int tid = threadIdx.x;

    if (b < PREP_CONV_BLOCKS) {
        int i = b * 256 + tid;
        if (i < N_NODES * 32) {
            float4 v = __ldg(&h4[i]);
            __half2 a = __floats2half2_rn(v.x, v.y);
            __half2 c = __floats2half2_rn(v.z, v.w);
            uint2 o;
            o.x = *reinterpret_cast<unsigned*>(&a);
            o.y = *reinterpret_cast<unsigned*>(&c);
            g_h16[i] = o;
        }
    } else if (b < PREP_CONV_BLOCKS + PREP_HIST_BLOCKS) {
        int t  = (b - PREP_CONV_BLOCKS) * 256 + tid;   // 4 edges per thread
        int4 d4 = __ldg(&((const int4*)dst)[t]);
        int r0 = atomicAdd(&g_cnt[d4.x], 1);
        int r1 = atomicAdd(&g_cnt[d4.y], 1);
        int r2 = atomicAdd(&g_cnt[d4.z], 1);
        int r3 = atomicAdd(&g_cnt[d4.w], 1);
        ((int4*)g_rank)[t] = make_int4(r0, r1, r2, r3);
    } else {
        int idx = (b - PREP_CONV_BLOCKS - PREP_HIST_BLOCKS) * 256 + tid;  // 24576
        int tg = idx & 3;
        int n  = (idx >> 2) & 127;
        int k0 = idx >> 9;
        g_wr[idx] = make_float2(__ldg(&W[n * D_IN3 + k0 * 8 + tg]),
                                __ldg(&W[n * D_IN3 + k0 * 8 + tg + 4]));
    }
}

// ---------------- single-block prefix scan + norm + counter reset -------------
__global__ void __launch_bounds__(1024) scan_kernel() {
    __shared__ int ts[1024];
    int t = threadIdx.x;
    if (t == 0) { g_ctrA = 0; g_ctrB = 0; }
    int b = t * 10;
    int e = min(b + 10, N_NODES);

    int s = 0;
    for (int i = b; i < e; i++) s += g_cnt[i];
    ts[t] = s;
    __syncthreads();

    for (int o = 1; o < 1024; o <<= 1) {
        int v = (t >= o) ? ts[t - o] : 0;
        __syncthreads();
        ts[t] += v;
        __syncthreads();
    }
    int off = (t == 0) ? 0 : ts[t - 1];

    for (int i = b; i < e; i++) {
        int c = g_cnt[i];
        g_row[i]  = off;
        g_norm[i] = rsqrtf(fmaxf((float)c, 1.0f));
        off += c;
    }
    if (t == 1023) g_row[N_NODES] = N_EDGES;
}

// ---------------- scatter edges into CSR order (NO atomics) -------------------
// Also zeroes g_cnt for the NEXT invocation (g_cnt is zero-initialized at
// module load, so every call sees cnt==0 at entry; deterministic).
__global__ void __launch_bounds__(256) scatter_kernel(
    const float* __restrict__ ew,
    const int*   __restrict__ src,
    const int*   __restrict__ dst)
{
    int t = blockIdx.x * blockDim.x + threadIdx.x;   // 4 edges per thread
    int4   d4 = __ldg(&((const int4*)dst)[t]);
    int4   s4 = __ldg(&((const int4*)src)[t]);
    float4 w4 = __ldg(&((const float4*)ew)[t]);
    int4   r4 = __ldg(&((const int4*)g_rank)[t]);

    int p0 = __ldg(&g_row[d4.x]) + r4.x;
    int p1 = __ldg(&g_row[d4.y]) + r4.y;
    int p2 = __ldg(&g_row[d4.z]) + r4.z;
    int p3 = __ldg(&g_row[d4.w]) + r4.w;

    float n0 = __ldg(&g_norm[s4.x]);
    float n1 = __ldg(&g_norm[s4.y]);
    float n2 = __ldg(&g_norm[s4.z]);
    float n3 = __ldg(&g_norm[s4.w]);

    float c10 = w4.x * n0, c11 = w4.y * n1, c12 = w4.z * n2, c13 = w4.w * n3;

    g_erec[p0] = make_int4(s4.x * 256, __float_as_int(c10), __float_as_int(c10 * n0), 0);
    g_erec[p1] = make_int4(s4.y * 256, __float_as_int(c11), __float_as_int(c11 * n1), 0);
    g_erec[p2] = make_int4(s4.z * 256, __float_as_int(c12), __float_as_int(c12 * n2), 0);
    g_erec[p3] = make_int4(s4.w * 256, __float_as_int(c13), __float_as_int(c13 * n3), 0);

    // reset histogram for next launch (scan has already consumed it)
    if (t < N_NODES / 4) ((int4*)g_cnt)[t] = make_int4(0, 0, 0, 0);
}

// ---------------- gather hop: half-warp per edge (2 edges / warp-iteration) ---
// Half h (lanes 16h..16h+15) owns one edge per pair; lane sub=lane&15 gathers
// uint4 (16B = 8 halves). 4 blocks/SM -> 64 regs for deeper LDG batching.
template <int SECOND>
__global__ void __launch_bounds__(256, 4) hop_csr(
    const uint2* __restrict__ feat16,
    unsigned*    __restrict__ ctr,
    uint4*       __restrict__ outh4)
{
    __shared__ __align__(8) uint2 stage[8][32];   // {byte_off, coef_bits}

    int lane = threadIdx.x & 31;
    int warp = threadIdx.x >> 5;
    int half = lane >> 4;          // 0 or 1
    int sub  = lane & 15;          // 0..15
    uint2* sbuf = stage[warp];
    const char* fbase = (const char*)feat16 + sub * 16;

    for (;;) {
        unsigned node = 0;
        if (lane == 0) node = atomicAdd(ctr, 1u);
        node = __shfl_sync(0xffffffffu, node, 0);
        if (node >= N_NODES) break;

        int beg = g_row[node];
        int end = g_row[node + 1];

        unsigned long long a0 = 0, a1 = 0, a2 = 0, a3 = 0;
        int base = beg;

        for (; base + 32 <= end; base += 32) {
            int4 rec = __ldg(&g_erec[base + lane]);
            unsigned cb = SECOND ? (unsigned)rec.z : (unsigned)rec.y;
            __syncwarp();
            sbuf[lane] = make_uint2((unsigned)rec.x, cb);
            __syncwarp();
#pragma unroll
            for (int i = 0; i < 16; i++) {
                uint2 e = sbuf[2 * i + half];            // LDS.64, 2-addr bcast
                unsigned long long cc;
                asm("mov.b64 %0, {%1, %1};" : "=l"(cc) : "r"(e.y));
                uint4 v = __ldg((const uint4*)(fbase + e.x));
                float2 f0 = __half22float2(*reinterpret_cast<__half2*>(&v.x));
                float2 f1 = __half22float2(*reinterpret_cast<__half2*>(&v.y));
                float2 f2 = __half22float2(*reinterpret_cast<__half2*>(&v.z));
                float2 f3 = __half22float2(*reinterpret_cast<__half2*>(&v.w));
                unsigned long long p0, p1, p2, p3;
                asm("mov.b64 %0, {%1, %2};" : "=l"(p0) : "f"(f0.x), "f"(f0.y));
                asm("mov.b64 %0, {%1, %2};" : "=l"(p1) : "f"(f1.x), "f"(f1.y));
                asm("mov.b64 %0, {%1, %2};" : "=l"(p2) : "f"(f2.x), "f"(f2.y));
                asm("mov.b64 %0, {%1, %2};" : "=l"(p3) : "f"(f3.x), "f"(f3.y));
                asm("fma.rn.f32x2 %0, %1, %2, %0;" : "+l"(a0) : "l"(cc), "l"(p0));
                asm("fma.rn.f32x2 %0, %1, %2, %0;" : "+l"(a1) : "l"(cc), "l"(p1));
                asm("fma.rn.f32x2 %0, %1, %2, %0;" : "+l"(a2) : "l"(cc), "l"(p2));
                asm("fma.rn.f32x2 %0, %1, %2, %0;" : "+l"(a3) : "l"(cc), "l"(p3));
            }
        }

        int rem = end - base;
        if (rem > 0) {
            __syncwarp();
            if (lane < rem) {
                int4 rec = __ldg(&g_erec[base + lane]);
                unsigned cb = SECOND ? (unsigned)rec.z : (unsigned)rec.y;
                sbuf[lane] = make_uint2((unsigned)rec.x, cb);
            } else {
                sbuf[lane] = make_uint2(0u, 0u);
            }
            __syncwarp();
            int pairs = (rem + 1) >> 1;
            for (int i = 0; i < pairs; i++) {
                uint2 e = sbuf[2 * i + half];
                unsigned long long cc;
                asm("mov.b64 %0, {%1, %1};" : "=l"(cc) : "r"(e.y));
                uint4 v = __ldg((const uint4*)(fbase + e.x));
                float2 f0 = __half22float2(*reinterpret_cast<__half2*>(&v.x));
                float2 f1 = __half22float2(*reinterpret_cast<__half2*>(&v.y));
                float2 f2 = __half22float2(*reinterpret_cast<__half2*>(&v.z));
                float2 f3 = __half22float2(*reinterpret_cast<__half2*>(&v.w));
                unsigned long long p0, p1, p2, p3;
                asm("mov.b64 %0, {%1, %2};" : "=l"(p0) : "f"(f0.x), "f"(f0.y));
                asm("mov.b64 %0, {%1, %2};" : "=l"(p1) : "f"(f1.x), "f"(f1.y));
                asm("mov.b64 %0, {%1, %2};" : "=l"(p2) : "f"(f2.x), "f"(f2.y));
                asm("mov.b64 %0, {%1, %2};" : "=l"(p3) : "f"(f3.x), "f"(f3.y));
                asm("fma.rn.f32x2 %0, %1, %2, %0;" : "+l"(a0) : "l"(cc), "l"(p0));
                asm("fma.rn.f32x2 %0, %1, %2, %0;" : "+l"(a1) : "l"(cc), "l"(p1));
                asm("fma.rn.f32x2 %0, %1, %2, %0;" : "+l"(a2) : "l"(cc), "l"(p2));
                asm("fma.rn.f32x2 %0, %1, %2, %0;" : "+l"(a3) : "l"(cc), "l"(p3));
            }
        }

        // merge even/odd-edge halves: lanes l and l^16 hold the two partials
        {
            unsigned long long b0 = __shfl_xor_sync(0xffffffffu, a0, 16);
            unsigned long long b1 = __shfl_xor_sync(0xffffffffu, a1, 16);
            unsigned long long b2 = __shfl_xor_sync(0xffffffffu, a2, 16);
            unsigned long long b3 = __shfl_xor_sync(0xffffffffu, a3, 16);
            asm("add.rn.f32x2 %0, %0, %1;" : "+l"(a0) : "l"(b0));
            asm("add.rn.f32x2 %0, %0, %1;" : "+l"(a1) : "l"(b1));
            asm("add.rn.f32x2 %0, %0, %1;" : "+l"(a2) : "l"(b2));
            asm("add.rn.f32x2 %0, %0, %1;" : "+l"(a3) : "l"(b3));
        }

        if (half == 0) {
            float x0, x1, x2, x3, x4, x5, x6, x7;
            asm("mov.b64 {%0, %1}, %2;" : "=f"(x0), "=f"(x1) : "l"(a0));
            asm("mov.b64 {%0, %1}, %2;" : "=f"(x2), "=f"(x3) : "l"(a1));
            asm("mov.b64 {%0, %1}, %2;" : "=f"(x4), "=f"(x5) : "l"(a2));
            asm("mov.b64 {%0, %1}, %2;" : "=f"(x6), "=f"(x7) : "l"(a3));
            __half2 h0 = __floats2half2_rn(x0, x1);
            __half2 h1 = __floats2half2_rn(x2, x3);
            __half2 h2 = __floats2half2_rn(x4, x5);
            __half2 h3 = __floats2half2_rn(x6, x7);
            uint4 o;
            o.x = *reinterpret_cast<unsigned*>(&h0);
            o.y = *reinterpret_cast<unsigned*>(&h1);
            o.z = *reinterpret_cast<unsigned*>(&h2);
            o.w = *reinterpret_cast<unsigned*>(&h3);
            outh4[node * 16 + sub] = o;
        }
    }
}

// ---------------- 3xTF32 helpers ---------------------------------------------
__device__ __forceinline__ unsigned f2tf(float x) {
    unsigned r;
    asm("cvt.rna.tf32.f32 %0, %1;" : "=r"(r) : "f"(x));
    return r;
}

__device__ __forceinline__ void mma8(float* d, const unsigned* a, const unsigned* b) {
    asm volatile("mma.sync.aligned.m16n8k8.row.col.f32.tf32.tf32.f32 "
                 "{%0,%1,%2,%3},{%4,%5,%6,%7},{%8,%9},{%0,%1,%2,%3};"
                 : "+f"(d[0]), "+f"(d[1]), "+f"(d[2]), "+f"(d[3])
                 : "r"(a[0]), "r"(a[1]), "r"(a[2]), "r"(a[3]),
                   "r"(b[0]), "r"(b[1]));
}

// ---------------- fused GEMM (3xTF32 mma) + bias + LayerNorm + ReLU ----------
// 256 threads (8 warps), TM=32 (best-measured config: 2 resident blocks/SM).
#define SAPAD 388
#define SXPAD 132
#define OUT_SMEM ((32 * SAPAD + 32 * SXPAD + 64) * 4)

__global__ void __launch_bounds__(256) out_kernel(
    const float* __restrict__ h,
    const float* __restrict__ bias,
    const float* __restrict__ gamma,
    const float* __restrict__ beta,
    float* __restrict__ out)
{
    constexpr int TM = 32;
    extern __shared__ float dyn[];
    float* sA  = dyn;                       // [TM][SAPAD]
    float* sx  = dyn + TM * SAPAD;          // [TM][SXPAD]
    float* smu = sx + TM * SXPAD;           // [TM]
    float* srs = smu + TM;                  // [TM]

    int tid   = threadIdx.x;
    int warp  = tid >> 5;
    int lane  = tid & 31;
    int node0 = blockIdx.x * TM;

    for (int idx = tid; idx < TM * 96; idx += 256) {
        int m = idx / 96, c = idx % 96;
        int node = min(node0 + m, N_NODES - 1);
        float4 v;
        if (c < 32) {
            v = __ldg(&((const float4*)h)[node * 32 + c]);
        } else {
            float nn = g_norm[node];
            const uint2* p16 = (c < 64) ? g_f1h : g_f2h;
            int cc = (c < 64) ? (c - 32) : (c - 64);
            uint2 u = p16[node * 32 + cc];
            float2 a = __half22float2(*reinterpret_cast<__half2*>(&u.x));
            float2 b = __half22float2(*reinterpret_cast<__half2*>(&u.y));
            v = make_float4(a.x * nn, a.y * nn, b.x * nn, b.y * nn);
        }
        *(float4*)&sA[m * SAPAD + c * 4] = v;
    }
    __syncthreads();

    int g  = lane >> 2;     // group 0..7
    int tg = lane & 3;      // thread-in-group 0..3
    int mrow = (warp >> 2) * 16;
    int wcol = (warp & 3) * 32;

    float acc[4][4];
#pragma unroll
    for (int nt = 0; nt < 4; nt++)
#pragma unroll
        for (int i = 0; i < 4; i++) acc[nt][i] = 0.0f;

#pragma unroll 4
    for (int k0 = 0; k0 < 48; k0++) {
        int kk = k0 * 8;
        float a0 = sA[(mrow + g    ) * SAPAD + kk + tg];
        float a1 = sA[(mrow + g + 8) * SAPAD + kk + tg];
        float a2 = sA[(mrow + g    ) * SAPAD + kk + tg + 4];
        float a3 = sA[(mrow + g + 8) * SAPAD + kk + tg + 4];

        unsigned ah[4] = { f2tf(a0), f2tf(a1), f2tf(a2), f2tf(a3) };
        unsigned al[4] = {
            f2tf(a0 - __uint_as_float(ah[0])),
            f2tf(a1 - __uint_as_float(ah[1])),
            f2tf(a2 - __uint_as_float(ah[2])),
            f2tf(a3 - __uint_as_float(ah[3]))
        };

#pragma unroll
        for (int nt = 0; nt < 4; nt++) {
            float2 wv = __ldg(&g_wr[k0 * 512 + (wcol + nt * 8) * 4 + lane]);
            unsigned bh[2] = { f2tf(wv.x), f2tf(wv.y) };
            unsigned bl[2] = {
                f2tf(wv.x - __uint_as_float(bh[0])),
                f2tf(wv.y - __uint_as_float(bh[1]))
            };
            mma8(acc[nt], ah, bh);
            mma8(acc[nt], al, bh);
            mma8(acc[nt], ah, bl);
        }
    }

#pragma unroll
    for (int nt = 0; nt < 4; nt++) {
        int col = wcol + nt * 8 + 2 * tg;
        float b0 = __ldg(&bias[col]);
        float b1 = __ldg(&bias[col + 1]);
        sx[(mrow + g    ) * SXPAD + col    ] = acc[nt][0] + b0;
        sx[(mrow + g    ) * SXPAD + col + 1] = acc[nt][1] + b1;
        sx[(mrow + g + 8) * SXPAD + col    ] = acc[nt][2] + b0;
        sx[(mrow + g + 8) * SXPAD + col + 1] = acc[nt][3] + b1;
    }
    __syncthreads();

    for (int m = warp; m < TM; m += 8) {
        float s = 0.0f, ss = 0.0f;
#pragma unroll
        for (int c = lane; c < D; c += 32) {
            float v = sx[m * SXPAD + c];
            s += v; ss += v * v;
        }
#pragma unroll
        for (int o = 16; o; o >>= 1) {
            s  += __shfl_xor_sync(0xffffffffu, s,  o);
            ss += __shfl_xor_sync(0xffffffffu, ss, o);
        }
        if (lane == 0) {
            float mu  = s * (1.0f / D);
            float var = ss * (1.0f / D) - mu * mu;
            smu[m] = mu;
            srs[m] = rsqrtf(var + LN_EPS);
        }
    }
    __syncthreads();

    int j     = tid & 127;
    int mbase = (tid >> 7) * 16;
    float gm = __ldg(&gamma[j]);
    float be = __ldg(&beta[j]);
#pragma unroll
    for (int mm = 0; mm < 16; mm++) {
        int m = mbase + mm;
        int node = node0 + m;
        if (node < N_NODES) {
            float v = (sx[m * SXPAD + j] - smu[m]) * srs[m] * gm + be;
            out[node * D + j] = fmaxf(v, 0.0f);
        }
    }
}

// ---------------- launch -----------------------------------------------------
extern "C" void kernel_launch(void* const* d_in, const int* in_sizes, int n_in,
                              void* d_out, int out_size)
{
    const float* h     = (const float*)d_in[0];
    const float* ew    = (const float*)d_in[1];
    const float* W     = (const float*)d_in[2];
    const float* bias  = (const float*)d_in[3];
    const float* gamma = (const float*)d_in[4];
    const float* beta  = (const float*)d_in[5];
    const int*   src   = (const int*)d_in[6];
    const int*   dst   = (const int*)d_in[7];
    float*       out   = (float*)d_out;

    void* h16Ptr;  cudaGetSymbolAddress(&h16Ptr,  g_h16);
    void* f1hPtr;  cudaGetSymbolAddress(&f1hPtr,  g_f1h);
    void* f2hPtr;  cudaGetSymbolAddress(&f2hPtr,  g_f2h);
    void* ctrAPtr; cudaGetSymbolAddress(&ctrAPtr, g_ctrA);
    void* ctrBPtr; cudaGetSymbolAddress(&ctrBPtr, g_ctrB);

    static bool attr_set = false;
    if (!attr_set) {
        cudaFuncSetAttribute(out_kernel,
                             cudaFuncAttributeMaxDynamicSharedMemorySize, OUT_SMEM);
        attr_set = true;
    }

    prep_kernel<<<PREP_BLOCKS, 256>>>((const float4*)h, dst, W);
    scan_kernel<<<1, 1024>>>();
    scatter_kernel<<<N_EDGES / 4 / 256, 256>>>(ew, src, dst);

    const int hopBlocks = 592;   // 4 blocks/SM * 148 SMs, persistent warps
    hop_csr<0><<<hopBlocks, 256>>>((const uint2*)h16Ptr, (unsigned*)ctrAPtr, (uint4*)f1hPtr);
    hop_csr<1><<<hopBlocks, 256>>>((const uint2*)f1hPtr, (unsigned*)ctrBPtr, (uint4*)f2hPtr);

    out_kernel<<<(N_NODES + 31) / 32, 256, OUT_SMEM>>>(h, bias, gamma, beta, out);
}

// round 16
// speedup vs baseline: 1.4520x; 1.2619x over previous
#include <cuda_runtime.h>
#include <cuda_fp16.h>

#define N_NODES 10000
#define N_EDGES 640000
#define D       128
#define D_IN3   384   // (K_HOPS+1)*D
#define LN_EPS  1e-5f

// ---------------- scratch (device globals; no allocation allowed) -----------
__device__ int      g_cnt [N_NODES];        // in-degree histogram (zeroed by scatter for next call)
__device__ int      g_row [N_NODES + 1];    // CSR row offsets (by dst)
__device__ float    g_norm[N_NODES];
__device__ int      g_rank[N_EDGES];        // edge rank within its dst segment
__device__ int4     g_erec[N_EDGES];        // {src*256, c1, c2, 0} sorted by dst
__device__ uint2    g_h16 [N_NODES * 32];   // h  as fp16 (256B rows)
__device__ uint2    g_f1h [N_NODES * 32];   // f1 as fp16
__device__ uint2    g_f2h [N_NODES * 32];   // f2 as fp16
__device__ uint2    g_wh  [24 * 512];       // W fp16 hi, mma-fragment layout [k0][n][tg]
__device__ uint2    g_wl  [24 * 512];       // W fp16 residual (lo)
__device__ unsigned g_ctrA, g_ctrB;         // hop work counters

// ---------------- fused prep: h->fp16 conv | dst hist+rank | W split ----------
#define PREP_CONV_BLOCKS 1250
#define PREP_HIST_BLOCKS 625
#define PREP_WR_BLOCKS   48
#define PREP_BLOCKS (PREP_CONV_BLOCKS + PREP_HIST_BLOCKS + PREP_WR_BLOCKS)

__global__ void __launch_bounds__(256) prep_kernel(
    const float4* __restrict__ h4,
    const int*    __restrict__ dst,
    const float*  __restrict__ W)
{
    int b   = blockIdx.x;
    int tid = threadIdx.x;

    if (b < PREP_CONV_BLOCKS) {
        int i = b * 256 + tid;
        if (i < N_NODES * 32) {
            float4 v = __ldg(&h4[i]);
            __half2 a = __floats2half2_rn(v.x, v.y);
            __half2 c = __floats2half2_rn(v.z, v.w);
            uint2 o;
            o.x = *reinterpret_cast<unsigned*>(&a);
            o.y = *reinterpret_cast<unsigned*>(&c);
            g_h16[i] = o;
        }
    } else if (b < PREP_CONV_BLOCKS + PREP_HIST_BLOCKS) {
        int t  = (b - PREP_CONV_BLOCKS) * 256 + tid;   // 4 edges per thread
        int4 d4 = __ldg(&((const int4*)dst)[t]);
        int r0 = atomicAdd(&g_cnt[d4.x], 1);
        int r1 = atomicAdd(&g_cnt[d4.y], 1);
        int r2 = atomicAdd(&g_cnt[d4.z], 1);
        int r3 = atomicAdd(&g_cnt[d4.w], 1);
        ((int4*)g_rank)[t] = make_int4(r0, r1, r2, r3);
    } else {
        // W split into fp16 hi + fp16 residual, packed per mma-B-fragment:
        // idx = k0*512 + n*4 + tg; thread covers k = 16k0 + {2tg,2tg+1,2tg+8,2tg+9}
        int idx = (b - PREP_CONV_BLOCKS - PREP_HIST_BLOCKS) * 256 + tid;  // 12288
        int tg = idx & 3;
        int n  = (idx >> 2) & 127;
        int k0 = idx >> 9;
        int kb = k0 * 16 + tg * 2;
        float w0 = __ldg(&W[n * D_IN3 + kb]);
        float w1 = __ldg(&W[n * D_IN3 + kb + 1]);
        float w2 = __ldg(&W[n * D_IN3 + kb + 8]);
        float w3 = __ldg(&W[n * D_IN3 + kb + 9]);
        __half h0 = __float2half_rn(w0), h1 = __float2half_rn(w1);
        __half h2 = __float2half_rn(w2), h3 = __float2half_rn(w3);
        __half2 bh0 = __halves2half2(h0, h1);
        __half2 bh1 = __halves2half2(h2, h3);
        __half2 bl0 = __floats2half2_rn(w0 - __half2float(h0), w1 - __half2float(h1));
        __half2 bl1 = __floats2half2_rn(w2 - __half2float(h2), w3 - __half2float(h3));
        uint2 oh, ol;
        oh.x = *reinterpret_cast<unsigned*>(&bh0);
        oh.y = *reinterpret_cast<unsigned*>(&bh1);
        ol.x = *reinterpret_cast<unsigned*>(&bl0);
        ol.y = *reinterpret_cast<unsigned*>(&bl1);
        g_wh[idx] = oh;
        g_wl[idx] = ol;
    }
}

// ---------------- single-block prefix scan + norm + counter reset -------------
__global__ void __launch_bounds__(1024) scan_kernel() {
    __shared__ int ts[1024];
    int t = threadIdx.x;
    if (t == 0) { g_ctrA = 0; g_ctrB = 0; }
    int b = t * 10;
    int e = min(b + 10, N_NODES);

    int s = 0;
    for (int i = b; i < e; i++) s += g_cnt[i];
    ts[t] = s;
    __syncthreads();

    for (int o = 1; o < 1024; o <<= 1) {
        int v = (t >= o) ? ts[t - o] : 0;
        __syncthreads();
        ts[t] += v;
        __syncthreads();
    }
    int off = (t == 0) ? 0 : ts[t - 1];

    for (int i = b; i < e; i++) {
        int c = g_cnt[i];
        g_row[i]  = off;
        g_norm[i] = rsqrtf(fmaxf((float)c, 1.0f));
        off += c;
    }
    if (t == 1023) g_row[N_NODES] = N_EDGES;
}

// ---------------- scatter edges into CSR order (NO atomics) -------------------
// Also zeroes g_cnt for the NEXT invocation.
__global__ void __launch_bounds__(256) scatter_kernel(
    const float* __restrict__ ew,
    const int*   __restrict__ src,
    const int*   __restrict__ dst)
{
    int t = blockIdx.x * blockDim.x + threadIdx.x;   // 4 edges per thread
    int4   d4 = __ldg(&((const int4*)dst)[t]);
    int4   s4 = __ldg(&((const int4*)src)[t]);
    float4 w4 = __ldg(&((const float4*)ew)[t]);
    int4   r4 = __ldg(&((const int4*)g_rank)[t]);

    int p0 = __ldg(&g_row[d4.x]) + r4.x;
    int p1 = __ldg(&g_row[d4.y]) + r4.y;
    int p2 = __ldg(&g_row[d4.z]) + r4.z;
    int p3 = __ldg(&g_row[d4.w]) + r4.w;

    float n0 = __ldg(&g_norm[s4.x]);
    float n1 = __ldg(&g_norm[s4.y]);
    float n2 = __ldg(&g_norm[s4.z]);
    float n3 = __ldg(&g_norm[s4.w]);

    float c10 = w4.x * n0, c11 = w4.y * n1, c12 = w4.z * n2, c13 = w4.w * n3;

    g_erec[p0] = make_int4(s4.x * 256, __float_as_int(c10), __float_as_int(c10 * n0), 0);
    g_erec[p1] = make_int4(s4.y * 256, __float_as_int(c11), __float_as_int(c11 * n1), 0);
    g_erec[p2] = make_int4(s4.z * 256, __float_as_int(c12), __float_as_int(c12 * n2), 0);
    g_erec[p3] = make_int4(s4.w * 256, __float_as_int(c13), __float_as_int(c13 * n3), 0);

    if (t < N_NODES / 4) ((int4*)g_cnt)[t] = make_int4(0, 0, 0, 0);
}

// ---------------- gather hop: half-warp per edge (2 edges / warp-iteration) ---
template <int SECOND>
__global__ void __launch_bounds__(256, 4) hop_csr(
    const uint2* __restrict__ feat16,
    unsigned*    __restrict__ ctr,
    uint4*       __restrict__ outh4)
{
    __shared__ __align__(8) uint2 stage[8][32];   // {byte_off, coef_bits}

    int lane = threadIdx.x & 31;
    int warp = threadIdx.x >> 5;
    int half = lane >> 4;          // 0 or 1
    int sub  = lane & 15;          // 0..15
    uint2* sbuf = stage[warp];
    const char* fbase = (const char*)feat16 + sub * 16;

    for (;;) {
        unsigned node = 0;
        if (lane == 0) node = atomicAdd(ctr, 1u);
        node = __shfl_sync(0xffffffffu, node, 0);
        if (node >= N_NODES) break;

        int beg = g_row[node];
        int end = g_row[node + 1];

        unsigned long long a0 = 0, a1 = 0, a2 = 0, a3 = 0;
        int base = beg;

        for (; base + 32 <= end; base += 32) {
            int4 rec = __ldg(&g_erec[base + lane]);
            unsigned cb = SECOND ? (unsigned)rec.z : (unsigned)rec.y;
            __syncwarp();
            sbuf[lane] = make_uint2((unsigned)rec.x, cb);
            __syncwarp();
#pragma unroll
            for (int i = 0; i < 16; i++) {
                uint2 e = sbuf[2 * i + half];            // LDS.64, 2-addr bcast
                unsigned long long cc;
                asm("mov.b64 %0, {%1, %1};" : "=l"(cc) : "r"(e.y));
                uint4 v = __ldg((const uint4*)(fbase + e.x));
                float2 f0 = __half22float2(*reinterpret_cast<__half2*>(&v.x));
                float2 f1 = __half22float2(*reinterpret_cast<__half2*>(&v.y));
                float2 f2 = __half22float2(*reinterpret_cast<__half2*>(&v.z));
                float2 f3 = __half22float2(*reinterpret_cast<__half2*>(&v.w));
                unsigned long long p0, p1, p2, p3;
                asm("mov.b64 %0, {%1, %2};" : "=l"(p0) : "f"(f0.x), "f"(f0.y));
                asm("mov.b64 %0, {%1, %2};" : "=l"(p1) : "f"(f1.x), "f"(f1.y));
                asm("mov.b64 %0, {%1, %2};" : "=l"(p2) : "f"(f2.x), "f"(f2.y));
                asm("mov.b64 %0, {%1, %2};" : "=l"(p3) : "f"(f3.x), "f"(f3.y));
                asm("fma.rn.f32x2 %0, %1, %2, %0;" : "+l"(a0) : "l"(cc), "l"(p0));
                asm("fma.rn.f32x2 %0, %1, %2, %0;" : "+l"(a1) : "l"(cc), "l"(p1));
                asm("fma.rn.f32x2 %0, %1, %2, %0;" : "+l"(a2) : "l"(cc), "l"(p2));
                asm("fma.rn.f32x2 %0, %1, %2, %0;" : "+l"(a3) : "l"(cc), "l"(p3));
            }
        }

        int rem = end - base;
        if (rem > 0) {
            __syncwarp();
            if (lane < rem) {
                int4 rec = __ldg(&g_erec[base + lane]);
                unsigned cb = SECOND ? (unsigned)rec.z : (unsigned)rec.y;
                sbuf[lane] = make_uint2((unsigned)rec.x, cb);
            } else {
                sbuf[lane] = make_uint2(0u, 0u);
            }
            __syncwarp();
            int pairs = (rem + 1) >> 1;
            for (int i = 0; i < pairs; i++) {
                uint2 e = sbuf[2 * i + half];
                unsigned long long cc;
                asm("mov.b64 %0, {%1, %1};" : "=l"(cc) : "r"(e.y));
                uint4 v = __ldg((const uint4*)(fbase + e.x));
                float2 f0 = __half22float2(*reinterpret_cast<__half2*>(&v.x));
                float2 f1 = __half22float2(*reinterpret_cast<__half2*>(&v.y));
                float2 f2 = __half22float2(*reinterpret_cast<__half2*>(&v.z));
                float2 f3 = __half22float2(*reinterpret_cast<__half2*>(&v.w));
                unsigned long long p0, p1, p2, p3;
                asm("mov.b64 %0, {%1, %2};" : "=l"(p0) : "f"(f0.x), "f"(f0.y));
                asm("mov.b64 %0, {%1, %2};" : "=l"(p1) : "f"(f1.x), "f"(f1.y));
                asm("mov.b64 %0, {%1, %2};" : "=l"(p2) : "f"(f2.x), "f"(f2.y));
                asm("mov.b64 %0, {%1, %2};" : "=l"(p3) : "f"(f3.x), "f"(f3.y));
                asm("fma.rn.f32x2 %0, %1, %2, %0;" : "+l"(a0) : "l"(cc), "l"(p0));
                asm("fma.rn.f32x2 %0, %1, %2, %0;" : "+l"(a1) : "l"(cc), "l"(p1));
                asm("fma.rn.f32x2 %0, %1, %2, %0;" : "+l"(a2) : "l"(cc), "l"(p2));
                asm("fma.rn.f32x2 %0, %1, %2, %0;" : "+l"(a3) : "l"(cc), "l"(p3));
            }
        }

        {
            unsigned long long b0 = __shfl_xor_sync(0xffffffffu, a0, 16);
            unsigned long long b1 = __shfl_xor_sync(0xffffffffu, a1, 16);
            unsigned long long b2 = __shfl_xor_sync(0xffffffffu, a2, 16);
            unsigned long long b3 = __shfl_xor_sync(0xffffffffu, a3, 16);
            asm("add.rn.f32x2 %0, %0, %1;" : "+l"(a0) : "l"(b0));
            asm("add.rn.f32x2 %0, %0, %1;" : "+l"(a1) : "l"(b1));
            asm("add.rn.f32x2 %0, %0, %1;" : "+l"(a2) : "l"(b2));
            asm("add.rn.f32x2 %0, %0, %1;" : "+l"(a3) : "l"(b3));
        }

        if (half == 0) {
            float x0, x1, x2, x3, x4, x5, x6, x7;
            asm("mov.b64 {%0, %1}, %2;" : "=f"(x0), "=f"(x1) : "l"(a0));
            asm("mov.b64 {%0, %1}, %2;" : "=f"(x2), "=f"(x3) : "l"(a1));
            asm("mov.b64 {%0, %1}, %2;" : "=f"(x4), "=f"(x5) : "l"(a2));
            asm("mov.b64 {%0, %1}, %2;" : "=f"(x6), "=f"(x7) : "l"(a3));
            __half2 h0 = __floats2half2_rn(x0, x1);
            __half2 h1 = __floats2half2_rn(x2, x3);
            __half2 h2 = __floats2half2_rn(x4, x5);
            __half2 h3 = __floats2half2_rn(x6, x7);
            uint4 o;
            o.x = *reinterpret_cast<unsigned*>(&h0);
            o.y = *reinterpret_cast<unsigned*>(&h1);
            o.z = *reinterpret_cast<unsigned*>(&h2);
            o.w = *reinterpret_cast<unsigned*>(&h3);
            outh4[node * 16 + sub] = o;
        }
    }
}

// ---------------- fp16 mma helper --------------------------------------------
__device__ __forceinline__ void mma16h(float* d, unsigned a0, unsigned a1,
                                       unsigned a2, unsigned a3,
                                       unsigned b0, unsigned b1) {
    asm volatile("mma.sync.aligned.m16n8k16.row.col.f32.f16.f16.f32 "
                 "{%0,%1,%2,%3},{%4,%5,%6,%7},{%8,%9},{%0,%1,%2,%3};"
                 : "+f"(d[0]), "+f"(d[1]), "+f"(d[2]), "+f"(d[3])
                 : "r"(a0), "r"(a1), "r"(a2), "r"(a3), "r"(b0), "r"(b1));
}

// ---------------- fused GEMM (fp16 mma, split-B) + bias + LN + ReLU ----------
// A tile: raw fp16 features [h16|f1h|f2h], 784B row stride (bank-conflict-free
// fragments). Two accumulator sets: accA (h block, k0 0..7), accB (f1+f2,
// k0 8..23); combined as accA + norm[row]*accB + bias.
#define SA_ROWB 784            // bytes per A row (768 + 16 pad)
#define SXPAD   132
#define TM      32
#define OUT_SMEM (TM * SA_ROWB + (TM * SXPAD + 2 * TM) * 4)

__global__ void __launch_bounds__(256) out_kernel(
    const float* __restrict__ bias,
    const float* __restrict__ gamma,
    const float* __restrict__ beta,
    float* __restrict__ out)
{
    extern __shared__ __align__(16) char dynraw[];
    char*  sAb = dynraw;                                   // [TM][SA_ROWB] fp16
    float* sx  = (float*)(dynraw + TM * SA_ROWB);          // [TM][SXPAD]
    float* smu = sx + TM * SXPAD;                          // [TM]
    float* srs = smu + TM;                                 // [TM]

    int tid   = threadIdx.x;
    int warp  = tid >> 5;
    int lane  = tid & 31;
    int node0 = blockIdx.x * TM;

    // ---- load raw fp16 feature tile: 96 uint2 (8B) per node ----
    for (int idx = tid; idx < TM * 96; idx += 256) {
        int m = idx / 96, c = idx % 96;
        int node = min(node0 + m, N_NODES - 1);
        const uint2* srcp = (c < 32) ? g_h16 : ((c < 64) ? g_f1h : g_f2h);
        int cc = (c < 32) ? c : ((c < 64) ? (c - 32) : (c - 64));
        uint2 u = srcp[node * 32 + cc];
        *(uint2*)(sAb + m * SA_ROWB + c * 8) = u;
    }
    __syncthreads();

    int g  = lane >> 2;     // group 0..7
    int tg = lane & 3;      // thread-in-group 0..3
    int mrow = (warp >> 2) * 16;
    int wcol = (warp & 3) * 32;

    float accA[4][4], accB[4][4];
#pragma unroll
    for (int nt = 0; nt < 4; nt++)
#pragma unroll
        for (int i = 0; i < 4; i++) { accA[nt][i] = 0.0f; accB[nt][i] = 0.0f; }

    const char* arow0 = sAb + (mrow + g) * SA_ROWB + tg * 4;
    const char* arow8 = arow0 + 8 * SA_ROWB;

#pragma unroll
    for (int k0 = 0; k0 < 24; k0++) {
        int kb = k0 * 32;   // byte offset of this k-step within a row
        unsigned a0 = *(const unsigned*)(arow0 + kb);
        unsigned a1 = *(const unsigned*)(arow8 + kb);
        unsigned a2 = *(const unsigned*)(arow0 + kb + 16);
        unsigned a3 = *(const unsigned*)(arow8 + kb + 16);

        float (*acc)[4] = (k0 < 8) ? accA : accB;
#pragma unroll
        for (int nt = 0; nt < 4; nt++) {
            int bidx = k0 * 512 + (wcol + nt * 8) * 4 + lane;
            uint2 bh = __ldg(&g_wh[bidx]);
            uint2 bl = __ldg(&g_wl[bidx]);
            mma16h(acc[nt], a0, a1, a2, a3, bh.x, bh.y);
            mma16h(acc[nt], a0, a1, a2, a3, bl.x, bl.y);
        }
    }

    // ---- combine: x = accA + norm[row]*accB + bias ----
    float nlo = g_norm[min(node0 + mrow + g,     N_NODES - 1)];
    float nhi = g_norm[min(node0 + mrow + g + 8, N_NODES - 1)];
#pragma unroll
    for (int nt = 0; nt < 4; nt++) {
        int col = wcol + nt * 8 + 2 * tg;
        float b0 = __ldg(&bias[col]);
        float b1 = __ldg(&bias[col + 1]);
        sx[(mrow + g    ) * SXPAD + col    ] = accA[nt][0] + nlo * accB[nt][0] + b0;
        sx[(mrow + g    ) * SXPAD + col + 1] = accA[nt][1] + nlo * accB[nt][1] + b1;
        sx[(mrow + g + 8) * SXPAD + col    ] = accA[nt][2] + nhi * accB[nt][2] + b0;
        sx[(mrow + g + 8) * SXPAD + col + 1] = accA[nt][3] + nhi * accB[nt][3] + b1;
    }
    __syncthreads();

    for (int m = warp; m < TM; m += 8) {
        float s = 0.0f, ss = 0.0f;
#pragma unroll
        for (int c = lane; c < D; c += 32) {
            float v = sx[m * SXPAD + c];
            s += v; ss += v * v;
        }
#pragma unroll
        for (int o = 16; o; o >>= 1) {
            s  += __shfl_xor_sync(0xffffffffu, s,  o);
            ss += __shfl_xor_sync(0xffffffffu, ss, o);
        }
        if (lane == 0) {
            float mu  = s * (1.0f / D);
            float var = ss * (1.0f / D) - mu * mu;
            smu[m] = mu;
            srs[m] = rsqrtf(var + LN_EPS);
        }
    }
    __syncthreads();

    int j     = tid & 127;
    int mbase = (tid >> 7) * 16;
    float gm = __ldg(&gamma[j]);
    float be = __ldg(&beta[j]);
#pragma unroll
    for (int mm = 0; mm < 16; mm++) {
        int m = mbase + mm;
        int node = node0 + m;
        if (node < N_NODES) {
            float v = (sx[m * SXPAD + j] - smu[m]) * srs[m] * gm + be;
            out[node * D + j] = fmaxf(v, 0.0f);
        }
    }
}

// ---------------- launch -----------------------------------------------------
extern "C" void kernel_launch(void* const* d_in, const int* in_sizes, int n_in,
                              void* d_out, int out_size)
{
    const float* h     = (const float*)d_in[0];
    const float* ew    = (const float*)d_in[1];
    const float* W     = (const float*)d_in[2];
    const float* bias  = (const float*)d_in[3];
    const float* gamma = (const float*)d_in[4];
    const float* beta  = (const float*)d_in[5];
    const int*   src   = (const int*)d_in[6];
    const int*   dst   = (const int*)d_in[7];
    float*       out   = (float*)d_out;

    void* h16Ptr;  cudaGetSymbolAddress(&h16Ptr,  g_h16);
    void* f1hPtr;  cudaGetSymbolAddress(&f1hPtr,  g_f1h);
    void* f2hPtr;  cudaGetSymbolAddress(&f2hPtr,  g_f2h);
    void* ctrAPtr; cudaGetSymbolAddress(&ctrAPtr, g_ctrA);
    void* ctrBPtr; cudaGetSymbolAddress(&ctrBPtr, g_ctrB);

    static bool attr_set = false;
    if (!attr_set) {
        cudaFuncSetAttribute(out_kernel,
                             cudaFuncAttributeMaxDynamicSharedMemorySize, OUT_SMEM);
        attr_set = true;
    }

    prep_kernel<<<PREP_BLOCKS, 256>>>((const float4*)h, dst, W);
    scan_kernel<<<1, 1024>>>();
    scatter_kernel<<<N_EDGES / 4 / 256, 256>>>(ew, src, dst);

    const int hopBlocks = 592;   // 4 blocks/SM * 148 SMs, persistent warps
    hop_csr<0><<<hopBlocks, 256>>>((const uint2*)h16Ptr, (unsigned*)ctrAPtr, (uint4*)f1hPtr);
    hop_csr<1><<<hopBlocks, 256>>>((const uint2*)f1hPtr, (unsigned*)ctrBPtr, (uint4*)f2hPtr);

    out_kernel<<<(N_NODES + TM - 1) / TM, 256, OUT_SMEM>>>(bias, gamma, beta, out);
}